// round 8
// baseline (speedup 1.0000x reference)
#include <cuda_runtime.h>
#include <cuda_fp16.h>
#include <cstdint>

// ScaledDotProductAttention B=2,H=16,S=2048,D=64 fp32, TEMP=32.
// d_out = [output 2*16*2048*64][attention 2*16*2048*2048]
//
// R7 = R5 design with alignment fix (obuf stride 66 -> 68):
//  - fp16 m16n8k16 mma; single pass (unnormalized PV, invr applied at end)
//  - QK accumulator fragments reused in REGISTERS as PV A-fragments
//  - exp via ex2.approx with log2e folded into Q prescale
//  - fp16 scratch + in-kernel normalize tail for the attention output

#define S_LEN 2048
#define KTILES 16
#define NTHREADS 512
#define KSTR 80     // halfs (160B row)
#define VSTR 144    // halfs (288B row)
#define PSTR 144
#define OSTR 68     // floats; multiple of 4 -> float4-aligned rows

// smem byte offsets
#define KOFF   0         // 2 x 128 x 160B = 40960
#define VOFF   40960     // 2 x 64 x 288B  = 36864
#define POFF   77824     // P fp16 128x288B = 36864; reused as obuf 128x68 fp32 (34816)
#define REDOFF 114688    // 512 floats
#define INVOFF 116736    // 128 floats
#define MBOFF  117248    // 64 u32
#define SMEM_TOTAL 117504

__device__ __half KH_g[2L * 16 * 2048 * 64];     // K fp16, d 16-interleaved
__device__ __half VTH_g[2L * 16 * 64 * 2048];    // V^T fp16, s 16-interleaved
__device__ __half SCR_g[2L * 16 * 2048 * 2048];  // unnormalized exp(S), interleaved

__host__ __device__ __forceinline__ int p16(int c) {
    return (c & ~15) | ((c & 6) << 1) | (c & 1) | ((c & 8) >> 2);
}

__device__ __forceinline__ uint32_t packh2(float a, float b) {
    __half2 h = __floats2half2_rn(a, b);
    return *reinterpret_cast<uint32_t*>(&h);
}
__device__ __forceinline__ float ex2f(float x) {
    float y; asm("ex2.approx.f32 %0, %1;" : "=f"(y) : "f"(x)); return y;
}

__device__ __forceinline__ void cp16(uint32_t dst, const void* src) {
    asm volatile("cp.async.cg.shared.global [%0], [%1], 16;" :: "r"(dst), "l"(src));
}
#define CP_COMMIT() asm volatile("cp.async.commit_group;" ::: "memory")
#define CP_WAIT0()  asm volatile("cp.async.wait_group 0;" ::: "memory")

__device__ __forceinline__ void mma16(float c[4], const uint32_t a[4], const uint32_t b[2]) {
    asm volatile(
        "mma.sync.aligned.m16n8k16.row.col.f32.f16.f16.f32 "
        "{%0,%1,%2,%3}, {%4,%5,%6,%7}, {%8,%9}, {%0,%1,%2,%3};\n"
        : "+f"(c[0]), "+f"(c[1]), "+f"(c[2]), "+f"(c[3])
        : "r"(a[0]), "r"(a[1]), "r"(a[2]), "r"(a[3]),
          "r"(b[0]), "r"(b[1]));
}

// ---------------- preprocessing ----------------

__global__ void prep_k(const float* __restrict__ k) {
    long i = (long)blockIdx.x * 256 + threadIdx.x;
    float4 v = reinterpret_cast<const float4*>(k)[i];
    long row = i >> 4;
    int c0 = (int)(i & 15) << 2;
    __half* dst = KH_g + row * 64;
    *reinterpret_cast<uint32_t*>(dst + p16(c0))     = packh2(v.x, v.y);
    *reinterpret_cast<uint32_t*>(dst + p16(c0 + 2)) = packh2(v.z, v.w);
}

__global__ void prep_v(const float* __restrict__ v) {
    __shared__ float sm[64][65];
    int bh = blockIdx.y;
    int s0 = blockIdx.x * 64;
    const float4* src = reinterpret_cast<const float4*>(v + ((long)bh * S_LEN + s0) * 64);
    for (int i = threadIdx.x; i < 64 * 16; i += 256) {
        int r = i >> 4, c4 = (i & 15) << 2;
        float4 val = src[i];
        sm[r][c4 + 0] = val.x; sm[r][c4 + 1] = val.y;
        sm[r][c4 + 2] = val.z; sm[r][c4 + 3] = val.w;
    }
    __syncthreads();
    __half* dst = VTH_g + (long)bh * 64 * S_LEN;
    for (int i = threadIdx.x; i < 64 * 16; i += 256) {
        int d = i >> 4, sl4 = (i & 15) << 2;
        __half* drow = dst + (long)d * S_LEN + s0;
        *reinterpret_cast<uint32_t*>(drow + p16(sl4)) =
            packh2(sm[sl4 + 0][d], sm[sl4 + 1][d]);
        *reinterpret_cast<uint32_t*>(drow + p16(sl4 + 2)) =
            packh2(sm[sl4 + 2][d], sm[sl4 + 3][d]);
    }
}

// ---------------- main fused kernel ----------------

__global__ __launch_bounds__(NTHREADS, 1)
void attn_main(const float* __restrict__ q, const int* __restrict__ mask,
               float* __restrict__ out, float* __restrict__ attn)
{
    extern __shared__ char smc[];
    __half* ksh = (__half*)(smc + KOFF);
    __half* vsh = (__half*)(smc + VOFF);
    __half* psh = (__half*)(smc + POFF);
    float*  red = (float*)(smc + REDOFF);
    float*  inv_s = (float*)(smc + INVOFF);
    uint32_t* mbits = (uint32_t*)(smc + MBOFF);
    const uint32_t smb = (uint32_t)__cvta_generic_to_shared(smc);

    const int tid  = threadIdx.x;
    const int lane = tid & 31;
    const int w    = tid >> 5;
    const int wm   = w >> 2;          // 0..3 -> 32 q-rows
    const int wn   = w & 3;           // 0..3 -> 32-col s-slice
    const int g    = lane >> 2;
    const int cq   = lane & 3;

    const int qt = blockIdx.x, bh = blockIdx.y;
    const int b = bh >> 4, q0 = qt * 128;

    const __half* kH = KH_g + (long)bh * S_LEN * 64;
    const __half* vT = VTH_g + (long)bh * 64 * S_LEN;
    const int* mbase = mask + (long)b * S_LEN;
    float* obase = out + ((long)bh * S_LEN + q0) * 64;
    float* abase = attn ? attn + ((long)bh * S_LEN + q0) * (long)S_LEN : (float*)0;
    __half* scr  = SCR_g + ((long)bh * 16 + qt) * (16L * 16384);

#define LOAD_K(buf_, kt_) do { \
        const __half* s_ = kH + (long)(kt_) * 128 * 64; \
        uint32_t d_ = smb + KOFF + (buf_) * 20480; \
        _Pragma("unroll") \
        for (int i_ = 0; i_ < 2; i_++) { \
            int idx_ = tid + i_ * NTHREADS; \
            int r_ = idx_ >> 3, c_ = idx_ & 7; \
            cp16(d_ + r_ * 160 + c_ * 16, s_ + r_ * 64 + c_ * 8); \
        } \
    } while (0)

#define LOAD_V(buf_, kt_) do { \
        const __half* s_ = vT + (kt_) * 128; \
        uint32_t d_ = smb + VOFF + (buf_) * 18432; \
        _Pragma("unroll") \
        for (int i_ = 0; i_ < 2; i_++) { \
            int idx_ = tid + i_ * NTHREADS; \
            int r_ = idx_ >> 4, c_ = idx_ & 15; \
            cp16(d_ + r_ * 288 + c_ * 16, s_ + (long)r_ * S_LEN + c_ * 8); \
        } \
    } while (0)

    LOAD_K(0, 0);
    LOAD_V(0, 0);
    CP_COMMIT();

    if (w < 4) {
        for (int t = 0; t < KTILES; t++) {
            int mv = mbase[t * 128 + w * 32 + lane];
            uint32_t bits = __ballot_sync(0xffffffffu, mv != 0);
            if (lane == 0) mbits[t * 4 + w] = bits;
        }
    }

    // Q fragments fp16, prescaled by (1/32)*log2(e) so scores are log2-domain
    const float QSC = 0.03125f * 1.44269504088896f;
    uint32_t qf[2][4][4];
    {
        const float* qb = q + ((long)bh * S_LEN + q0 + wm * 32) * 64;
        #pragma unroll
        for (int mi = 0; mi < 2; mi++) {
            const float* r0p = qb + (mi * 16 + g) * 64;
            const float* r1p = r0p + 8 * 64;
            #pragma unroll
            for (int blk = 0; blk < 4; blk++) {
                int c0 = blk * 16 + 2 * cq;
                qf[mi][blk][0] = packh2(r0p[c0] * QSC,     r0p[c0 + 1] * QSC);
                qf[mi][blk][1] = packh2(r1p[c0] * QSC,     r1p[c0 + 1] * QSC);
                qf[mi][blk][2] = packh2(r0p[c0 + 8] * QSC, r0p[c0 + 9] * QSC);
                qf[mi][blk][3] = packh2(r1p[c0 + 8] * QSC, r1p[c0 + 9] * QSC);
            }
        }
    }

    float rs[2][2] = {{0.f, 0.f}, {0.f, 0.f}};
    float o[2][8][4];
    #pragma unroll
    for (int mi = 0; mi < 2; mi++)
        #pragma unroll
        for (int nd = 0; nd < 8; nd++)
            #pragma unroll
            for (int r = 0; r < 4; r++) o[mi][nd][r] = 0.f;

    for (int kt = 0; kt < KTILES; kt++) {
        CP_WAIT0();
        __syncthreads();
        int cb = kt & 1;
        if (kt + 1 < KTILES) {
            int nb = (kt + 1) & 1;
            LOAD_K(nb, kt + 1);
            LOAD_V(nb, kt + 1);
            CP_COMMIT();
        }

        // ---- S = (Q*log2e/32) K^T ----
        const __half* kb_ = ksh + cb * 128 * KSTR;
        float c[2][4][4];
        #pragma unroll
        for (int mi = 0; mi < 2; mi++)
            #pragma unroll
            for (int ni = 0; ni < 4; ni++)
                #pragma unroll
                for (int r = 0; r < 4; r++) c[mi][ni][r] = 0.f;

        #pragma unroll
        for (int blk = 0; blk < 4; blk++) {
            uint32_t bf[4][2];
            #pragma unroll
            for (int ni = 0; ni < 4; ni++) {
                uint2 t = *reinterpret_cast<const uint2*>(
                    kb_ + (wn * 32 + ni * 8 + g) * KSTR + blk * 16 + cq * 4);
                bf[ni][0] = t.x; bf[ni][1] = t.y;
            }
            #pragma unroll
            for (int mi = 0; mi < 2; mi++)
                #pragma unroll
                for (int ni = 0; ni < 4; ni++) mma16(c[mi][ni], qf[mi][blk], bf[ni]);
        }

        // ---- epilogue: e = 2^S (masked), rowsum accum, pack P in regs + stage smem ----
        uint32_t pa0[2][4], pa1[2][4];
        uint32_t word = mbits[kt * 4 + wn];
        #pragma unroll
        for (int ni = 0; ni < 4; ni++) {
            int j = ni * 8 + 2 * cq;
            int m0 = (word >> j) & 1, m1 = (word >> (j + 1)) & 1;
            int col = wn * 32 + j;
            int phys = (col & ~15) | ((2 * cq) << 1) | ((ni & 1) << 1);
            #pragma unroll
            for (int mi = 0; mi < 2; mi++) {
                int r0 = wm * 32 + mi * 16 + g;
                float e0 = m0 ? ex2f(c[mi][ni][0]) : 0.f;
                float e1 = m1 ? ex2f(c[mi][ni][1]) : 0.f;
                float e2 = m0 ? ex2f(c[mi][ni][2]) : 0.f;
                float e3 = m1 ? ex2f(c[mi][ni][3]) : 0.f;
                rs[mi][0] += e0 + e1;
                rs[mi][1] += e2 + e3;
                uint32_t h01 = packh2(e0, e1), h23 = packh2(e2, e3);
                pa0[mi][ni] = h01; pa1[mi][ni] = h23;
                *reinterpret_cast<uint32_t*>(psh + r0 * PSTR + phys)       = h01;
                *reinterpret_cast<uint32_t*>(psh + (r0 + 8) * PSTR + phys) = h23;
            }
        }

        // ---- O += P_unnorm @ V  (A-fragments from registers; no barrier) ----
        const __half* vb = vsh + cb * 64 * VSTR;
        #pragma unroll
        for (int bb = 0; bb < 2; bb++) {
            uint32_t bv[8][2];
            #pragma unroll
            for (int nd = 0; nd < 8; nd++) {
                uint2 t = *reinterpret_cast<const uint2*>(
                    vb + (nd * 8 + g) * VSTR + wn * 32 + bb * 16 + cq * 4);
                bv[nd][0] = t.x; bv[nd][1] = t.y;
            }
            #pragma unroll
            for (int mi = 0; mi < 2; mi++) {
                uint32_t a[4] = {pa0[mi][2 * bb], pa1[mi][2 * bb],
                                 pa0[mi][2 * bb + 1], pa1[mi][2 * bb + 1]};
                #pragma unroll
                for (int nd = 0; nd < 8; nd++) mma16(o[mi][nd], a, bv[nd]);
            }
        }

        __syncthreads();   // all P staged before coalesced scratch copy

        // ---- stage unnormalized exp tile to global scratch (coalesced) ----
        if (abase) {
            __half* sd = scr + (long)kt * 16384;
            #pragma unroll
            for (int i2 = 0; i2 < 4; i2++) {
                int f = tid + i2 * NTHREADS;
                int r = f >> 4, cc = f & 15;
                *reinterpret_cast<uint4*>(sd + f * 8) =
                    *reinterpret_cast<const uint4*>(
                        reinterpret_cast<const char*>(psh) + r * 288 + cc * 16);
            }
        }
    }

    // ---- rowsum reduce -> invr ----
    #pragma unroll
    for (int mi = 0; mi < 2; mi++)
        #pragma unroll
        for (int h = 0; h < 2; h++) {
            float s = rs[mi][h];
            s += __shfl_xor_sync(0xffffffffu, s, 1);
            s += __shfl_xor_sync(0xffffffffu, s, 2);
            if (cq == 0) red[wn * 128 + wm * 32 + mi * 16 + h * 8 + g] = s;
        }
    __syncthreads();
    if (tid < 128) {
        float t = red[tid] + red[128 + tid] + red[256 + tid] + red[384 + tid];
        inv_s[tid] = 1.0f / t;
    }
    __syncthreads();

    // ---- reduce partial O across the 4 wn warps via smem (reuses P region) ----
    float* obuf = (float*)(smc + POFF);   // 128 x OSTR fp32
    #pragma unroll
    for (int widx = 0; widx < 4; widx++) {
        if (wn == widx) {
            #pragma unroll
            for (int mi = 0; mi < 2; mi++) {
                int r0 = wm * 32 + mi * 16 + g;
                #pragma unroll
                for (int nd = 0; nd < 8; nd++) {
                    int dc = nd * 8 + 2 * cq;
                    float2* p0 = reinterpret_cast<float2*>(obuf + r0 * OSTR + dc);
                    float2* p1 = reinterpret_cast<float2*>(obuf + (r0 + 8) * OSTR + dc);
                    if (widx == 0) {
                        *p0 = make_float2(o[mi][nd][0], o[mi][nd][1]);
                        *p1 = make_float2(o[mi][nd][2], o[mi][nd][3]);
                    } else {
                        float2 t0 = *p0, t1 = *p1;
                        t0.x += o[mi][nd][0]; t0.y += o[mi][nd][1];
                        t1.x += o[mi][nd][2]; t1.y += o[mi][nd][3];
                        *p0 = t0; *p1 = t1;
                    }
                }
            }
        }
        __syncthreads();
    }

    // ---- normalize + write O ----
    #pragma unroll
    for (int i = 0; i < 4; i++) {
        int idx = tid + i * NTHREADS;       // 2048 float4 = 128 x 64
        int r = idx >> 4, c4 = (idx & 15) << 2;
        float iv = inv_s[r];
        float4 v4 = *reinterpret_cast<const float4*>(obuf + r * OSTR + c4);
        *reinterpret_cast<float4*>(obase + (long)r * 64 + c4) =
            make_float4(v4.x * iv, v4.y * iv, v4.z * iv, v4.w * iv);
    }

    // ---- tail: scratch (fp16, L2-warm) -> normalized fp32 attention ----
    if (abase) {
        for (int kt = 0; kt < KTILES; kt++) {
            const __half* ss = scr + (long)kt * 16384;
            #pragma unroll
            for (int i2 = 0; i2 < 2; i2++) {
                int idx = tid + i2 * NTHREADS;
                int r = idx >> 3, blk = idx & 7;
                float iv = inv_s[r];
                uint4 u0 = *reinterpret_cast<const uint4*>(ss + idx * 16);
                uint4 u1 = *reinterpret_cast<const uint4*>(ss + idx * 16 + 8);
                float2 f0 = __half22float2(*reinterpret_cast<__half2*>(&u0.x));
                float2 f1 = __half22float2(*reinterpret_cast<__half2*>(&u0.y));
                float2 f2 = __half22float2(*reinterpret_cast<__half2*>(&u0.z));
                float2 f3 = __half22float2(*reinterpret_cast<__half2*>(&u0.w));
                float2 f4 = __half22float2(*reinterpret_cast<__half2*>(&u1.x));
                float2 f5 = __half22float2(*reinterpret_cast<__half2*>(&u1.y));
                float2 f6 = __half22float2(*reinterpret_cast<__half2*>(&u1.z));
                float2 f7 = __half22float2(*reinterpret_cast<__half2*>(&u1.w));
                float4* dst = reinterpret_cast<float4*>(
                    abase + (long)r * S_LEN + kt * 128 + blk * 16);
                dst[0] = make_float4(f0.x * iv, f0.y * iv, f2.x * iv, f2.y * iv);
                dst[1] = make_float4(f4.x * iv, f4.y * iv, f6.x * iv, f6.y * iv);
                dst[2] = make_float4(f1.x * iv, f1.y * iv, f3.x * iv, f3.y * iv);
                dst[3] = make_float4(f5.x * iv, f5.y * iv, f7.x * iv, f7.y * iv);
            }
        }
    }
#undef LOAD_K
#undef LOAD_V
}

extern "C" void kernel_launch(void* const* d_in, const int* in_sizes, int n_in,
                              void* d_out, int out_size) {
    const float* q    = (const float*)d_in[0];
    const float* k    = (const float*)d_in[1];
    const float* v    = (const float*)d_in[2];
    const int*   mask = (const int*)d_in[3];

    float* out = (float*)d_out;
    const long OUT_ELEMS  = 2L * 16 * 2048 * 64;
    const long ATTN_ELEMS = 2L * 16 * 2048 * 2048;
    float* attn = ((long)out_size >= OUT_ELEMS + ATTN_ELEMS) ? out + OUT_ELEMS : nullptr;

    prep_k<<<4096, 256>>>(k);
    prep_v<<<dim3(32, 32), 256>>>(v);

    cudaFuncSetAttribute(attn_main, cudaFuncAttributeMaxDynamicSharedMemorySize, SMEM_TOTAL);
    attn_main<<<dim3(16, 32), NTHREADS, SMEM_TOTAL>>>(q, mask, out, attn);
}

// round 10
// speedup vs baseline: 1.2262x; 1.2262x over previous
#include <cuda_runtime.h>
#include <cuda_fp16.h>
#include <cstdint>

// ScaledDotProductAttention B=2,H=16,S=2048,D=64 fp32, TEMP=32.
// d_out = [output 2*16*2048*64][attention 2*16*2048*2048]
//
// R9: two-pass fp16 m16n8k16, NO scratch:
//  pass1: QK + ex2 -> rowsums (no stores)
//  pass2: QK recompute, P = ex2(S - log2(rowsum)) normalized in regs,
//         attention written directly from regs (st.global.cs),
//         fp16 P staged in smem, PV from smem (R4 mapping).
// Q prescaled by log2e/32 so scores are in log2 domain.

#define S_LEN 2048
#define KTILES 16
#define NTHREADS 512
#define KSTR 80     // halfs (160B row)
#define VSTR 144    // halfs (288B row)
#define PSTR 144

// smem byte offsets
#define KOFF   0         // 2 x 128 x 160B = 40960
#define VOFF   40960     // 2 x 64 x 288B  = 36864
#define POFF   77824     // P fp16 128x288B = 36864
#define REDOFF 114688    // 512 floats
#define L2OFF  116736    // 128 floats (log2 of rowsum)
#define MBOFF  117248    // 64 u32
#define SMEM_TOTAL 117504

__device__ __half KH_g[2L * 16 * 2048 * 64];     // K fp16, d 16-interleaved
__device__ __half VTH_g[2L * 16 * 64 * 2048];    // V^T fp16, s 16-interleaved

__host__ __device__ __forceinline__ int p16(int c) {
    return (c & ~15) | ((c & 6) << 1) | (c & 1) | ((c & 8) >> 2);
}

__device__ __forceinline__ uint32_t packh2(float a, float b) {
    __half2 h = __floats2half2_rn(a, b);
    return *reinterpret_cast<uint32_t*>(&h);
}
__device__ __forceinline__ float ex2f(float x) {
    float y; asm("ex2.approx.f32 %0, %1;" : "=f"(y) : "f"(x)); return y;
}
__device__ __forceinline__ float lg2f(float x) {
    float y; asm("lg2.approx.f32 %0, %1;" : "=f"(y) : "f"(x)); return y;
}
__device__ __forceinline__ void stcs2(float* p, float a, float b) {
    asm volatile("st.global.cs.v2.f32 [%0], {%1,%2};" :: "l"(p), "f"(a), "f"(b) : "memory");
}

__device__ __forceinline__ void cp16(uint32_t dst, const void* src) {
    asm volatile("cp.async.cg.shared.global [%0], [%1], 16;" :: "r"(dst), "l"(src));
}
#define CP_COMMIT() asm volatile("cp.async.commit_group;" ::: "memory")
#define CP_WAIT0()  asm volatile("cp.async.wait_group 0;" ::: "memory")

__device__ __forceinline__ void mma16(float c[4], const uint32_t a[4], const uint32_t b[2]) {
    asm volatile(
        "mma.sync.aligned.m16n8k16.row.col.f32.f16.f16.f32 "
        "{%0,%1,%2,%3}, {%4,%5,%6,%7}, {%8,%9}, {%0,%1,%2,%3};\n"
        : "+f"(c[0]), "+f"(c[1]), "+f"(c[2]), "+f"(c[3])
        : "r"(a[0]), "r"(a[1]), "r"(a[2]), "r"(a[3]),
          "r"(b[0]), "r"(b[1]));
}

// ---------------- preprocessing ----------------

__global__ void prep_k(const float* __restrict__ k) {
    long i = (long)blockIdx.x * 256 + threadIdx.x;
    float4 v = reinterpret_cast<const float4*>(k)[i];
    long row = i >> 4;
    int c0 = (int)(i & 15) << 2;
    __half* dst = KH_g + row * 64;
    *reinterpret_cast<uint32_t*>(dst + p16(c0))     = packh2(v.x, v.y);
    *reinterpret_cast<uint32_t*>(dst + p16(c0 + 2)) = packh2(v.z, v.w);
}

__global__ void prep_v(const float* __restrict__ v) {
    __shared__ float sm[64][65];
    int bh = blockIdx.y;
    int s0 = blockIdx.x * 64;
    const float4* src = reinterpret_cast<const float4*>(v + ((long)bh * S_LEN + s0) * 64);
    for (int i = threadIdx.x; i < 64 * 16; i += 256) {
        int r = i >> 4, c4 = (i & 15) << 2;
        float4 val = src[i];
        sm[r][c4 + 0] = val.x; sm[r][c4 + 1] = val.y;
        sm[r][c4 + 2] = val.z; sm[r][c4 + 3] = val.w;
    }
    __syncthreads();
    __half* dst = VTH_g + (long)bh * 64 * S_LEN;
    for (int i = threadIdx.x; i < 64 * 16; i += 256) {
        int d = i >> 4, sl4 = (i & 15) << 2;
        __half* drow = dst + (long)d * S_LEN + s0;
        *reinterpret_cast<uint32_t*>(drow + p16(sl4)) =
            packh2(sm[sl4 + 0][d], sm[sl4 + 1][d]);
        *reinterpret_cast<uint32_t*>(drow + p16(sl4 + 2)) =
            packh2(sm[sl4 + 2][d], sm[sl4 + 3][d]);
    }
}

// ---------------- main fused kernel ----------------

__global__ __launch_bounds__(NTHREADS, 1)
void attn_main(const float* __restrict__ q, const int* __restrict__ mask,
               float* __restrict__ out, float* __restrict__ attn)
{
    extern __shared__ char smc[];
    __half* ksh = (__half*)(smc + KOFF);
    __half* vsh = (__half*)(smc + VOFF);
    __half* psh = (__half*)(smc + POFF);
    float*  red = (float*)(smc + REDOFF);
    float*  l2s = (float*)(smc + L2OFF);
    uint32_t* mbits = (uint32_t*)(smc + MBOFF);
    const uint32_t smb = (uint32_t)__cvta_generic_to_shared(smc);

    const int tid  = threadIdx.x;
    const int lane = tid & 31;
    const int w    = tid >> 5;
    const int wm   = w >> 2;          // 0..3 -> 32 q-rows
    const int wn   = w & 3;           // 0..3 -> 32-col s-slice (QK) / 16 d-cols (PV)
    const int g    = lane >> 2;
    const int cq   = lane & 3;

    const int qt = blockIdx.x, bh = blockIdx.y;
    const int b = bh >> 4, q0 = qt * 128;

    const __half* kH = KH_g + (long)bh * S_LEN * 64;
    const __half* vT = VTH_g + (long)bh * 64 * S_LEN;
    const int* mbase = mask + (long)b * S_LEN;
    float* obase = out + ((long)bh * S_LEN + q0) * 64;
    float* abase = attn ? attn + ((long)bh * S_LEN + q0) * (long)S_LEN : (float*)0;

#define LOAD_K(buf_, kt_) do { \
        const __half* s_ = kH + (long)(kt_) * 128 * 64; \
        uint32_t d_ = smb + KOFF + (buf_) * 20480; \
        _Pragma("unroll") \
        for (int i_ = 0; i_ < 2; i_++) { \
            int idx_ = tid + i_ * NTHREADS; \
            int r_ = idx_ >> 3, c_ = idx_ & 7; \
            cp16(d_ + r_ * 160 + c_ * 16, s_ + r_ * 64 + c_ * 8); \
        } \
    } while (0)

#define LOAD_V(buf_, kt_) do { \
        const __half* s_ = vT + (kt_) * 128; \
        uint32_t d_ = smb + VOFF + (buf_) * 18432; \
        _Pragma("unroll") \
        for (int i_ = 0; i_ < 2; i_++) { \
            int idx_ = tid + i_ * NTHREADS; \
            int r_ = idx_ >> 4, c_ = idx_ & 15; \
            cp16(d_ + r_ * 288 + c_ * 16, s_ + (long)r_ * S_LEN + c_ * 8); \
        } \
    } while (0)

    LOAD_K(0, 0);
    CP_COMMIT();

    if (w < 4) {
        for (int t = 0; t < KTILES; t++) {
            int mv = mbase[t * 128 + w * 32 + lane];
            uint32_t bits = __ballot_sync(0xffffffffu, mv != 0);
            if (lane == 0) mbits[t * 4 + w] = bits;
        }
    }

    // Q fragments fp16, prescaled by (1/32)*log2(e): scores in log2 domain
    const float QSC = 0.03125f * 1.44269504088896f;
    uint32_t qf[2][4][4];
    {
        const float* qb = q + ((long)bh * S_LEN + q0 + wm * 32) * 64;
        #pragma unroll
        for (int mi = 0; mi < 2; mi++) {
            const float* r0p = qb + (mi * 16 + g) * 64;
            const float* r1p = r0p + 8 * 64;
            #pragma unroll
            for (int blk = 0; blk < 4; blk++) {
                int c0 = blk * 16 + 2 * cq;
                qf[mi][blk][0] = packh2(r0p[c0] * QSC,     r0p[c0 + 1] * QSC);
                qf[mi][blk][1] = packh2(r1p[c0] * QSC,     r1p[c0 + 1] * QSC);
                qf[mi][blk][2] = packh2(r0p[c0 + 8] * QSC, r0p[c0 + 9] * QSC);
                qf[mi][blk][3] = packh2(r1p[c0 + 8] * QSC, r1p[c0 + 9] * QSC);
            }
        }
    }

    // =========================== PASS 1: rowsums ===========================
    float rs[2][2] = {{0.f, 0.f}, {0.f, 0.f}};
    for (int kt = 0; kt < KTILES; kt++) {
        CP_WAIT0();
        __syncthreads();
        int cb = kt & 1;
        if (kt + 1 < KTILES) { LOAD_K((kt + 1) & 1, kt + 1); CP_COMMIT(); }

        const __half* kb_ = ksh + cb * 128 * KSTR;
        float c[2][4][4];
        #pragma unroll
        for (int mi = 0; mi < 2; mi++)
            #pragma unroll
            for (int ni = 0; ni < 4; ni++)
                #pragma unroll
                for (int r = 0; r < 4; r++) c[mi][ni][r] = 0.f;

        #pragma unroll
        for (int blk = 0; blk < 4; blk++) {
            uint32_t bf[4][2];
            #pragma unroll
            for (int ni = 0; ni < 4; ni++) {
                uint2 t = *reinterpret_cast<const uint2*>(
                    kb_ + (wn * 32 + ni * 8 + g) * KSTR + blk * 16 + cq * 4);
                bf[ni][0] = t.x; bf[ni][1] = t.y;
            }
            #pragma unroll
            for (int mi = 0; mi < 2; mi++)
                #pragma unroll
                for (int ni = 0; ni < 4; ni++) mma16(c[mi][ni], qf[mi][blk], bf[ni]);
        }

        uint32_t word = mbits[kt * 4 + wn];
        #pragma unroll
        for (int ni = 0; ni < 4; ni++) {
            int j = ni * 8 + 2 * cq;
            int m0 = (word >> j) & 1, m1 = (word >> (j + 1)) & 1;
            #pragma unroll
            for (int mi = 0; mi < 2; mi++) {
                rs[mi][0] += (m0 ? ex2f(c[mi][ni][0]) : 0.f) + (m1 ? ex2f(c[mi][ni][1]) : 0.f);
                rs[mi][1] += (m0 ? ex2f(c[mi][ni][2]) : 0.f) + (m1 ? ex2f(c[mi][ni][3]) : 0.f);
            }
        }
    }

    // prefetch pass2 tile 0 (K+V) so the DMA overlaps the reduction
    LOAD_K(0, 0);
    LOAD_V(0, 0);
    CP_COMMIT();

    // ---- rowsum reduce -> l2s = log2(rowsum) ----
    #pragma unroll
    for (int mi = 0; mi < 2; mi++)
        #pragma unroll
        for (int h = 0; h < 2; h++) {
            float s = rs[mi][h];
            s += __shfl_xor_sync(0xffffffffu, s, 1);
            s += __shfl_xor_sync(0xffffffffu, s, 2);
            if (cq == 0) red[wn * 128 + wm * 32 + mi * 16 + h * 8 + g] = s;
        }
    __syncthreads();
    if (tid < 128) {
        float t = red[tid] + red[128 + tid] + red[256 + tid] + red[384 + tid];
        l2s[tid] = lg2f(t);
    }
    __syncthreads();

    float l2v[2][2];
    #pragma unroll
    for (int mi = 0; mi < 2; mi++)
        #pragma unroll
        for (int h = 0; h < 2; h++)
            l2v[mi][h] = l2s[wm * 32 + mi * 16 + h * 8 + g];

    // ================== PASS 2: attention write + O = P V ==================
    float o[2][2][4];
    #pragma unroll
    for (int mi = 0; mi < 2; mi++)
        #pragma unroll
        for (int ni = 0; ni < 2; ni++)
            #pragma unroll
            for (int r = 0; r < 4; r++) o[mi][ni][r] = 0.f;

    for (int kt = 0; kt < KTILES; kt++) {
        CP_WAIT0();
        __syncthreads();
        int cb = kt & 1;
        if (kt + 1 < KTILES) {
            int nb = (kt + 1) & 1;
            LOAD_K(nb, kt + 1);
            LOAD_V(nb, kt + 1);
            CP_COMMIT();
        }

        // ---- S = (Q*log2e/32) K^T ----
        const __half* kb_ = ksh + cb * 128 * KSTR;
        float c[2][4][4];
        #pragma unroll
        for (int mi = 0; mi < 2; mi++)
            #pragma unroll
            for (int ni = 0; ni < 4; ni++)
                #pragma unroll
                for (int r = 0; r < 4; r++) c[mi][ni][r] = 0.f;

        #pragma unroll
        for (int blk = 0; blk < 4; blk++) {
            uint32_t bf[4][2];
            #pragma unroll
            for (int ni = 0; ni < 4; ni++) {
                uint2 t = *reinterpret_cast<const uint2*>(
                    kb_ + (wn * 32 + ni * 8 + g) * KSTR + blk * 16 + cq * 4);
                bf[ni][0] = t.x; bf[ni][1] = t.y;
            }
            #pragma unroll
            for (int mi = 0; mi < 2; mi++)
                #pragma unroll
                for (int ni = 0; ni < 4; ni++) mma16(c[mi][ni], qf[mi][blk], bf[ni]);
        }

        // ---- epilogue: p = 2^(S - log2 rowsum) masked; write attn; stage P ----
        uint32_t word = mbits[kt * 4 + wn];
        #pragma unroll
        for (int ni = 0; ni < 4; ni++) {
            int j = ni * 8 + 2 * cq;
            int m0 = (word >> j) & 1, m1 = (word >> (j + 1)) & 1;
            int col = wn * 32 + j;
            int phys = (col & ~15) | ((2 * cq) << 1) | ((ni & 1) << 1);
            #pragma unroll
            for (int mi = 0; mi < 2; mi++) {
                int r0 = wm * 32 + mi * 16 + g;
                float p0 = m0 ? ex2f(c[mi][ni][0] - l2v[mi][0]) : 0.f;
                float p1 = m1 ? ex2f(c[mi][ni][1] - l2v[mi][0]) : 0.f;
                float p2 = m0 ? ex2f(c[mi][ni][2] - l2v[mi][1]) : 0.f;
                float p3 = m1 ? ex2f(c[mi][ni][3] - l2v[mi][1]) : 0.f;
                *reinterpret_cast<uint32_t*>(psh + r0 * PSTR + phys)       = packh2(p0, p1);
                *reinterpret_cast<uint32_t*>(psh + (r0 + 8) * PSTR + phys) = packh2(p2, p3);
                if (abase) {
                    stcs2(abase + (long)r0 * S_LEN + kt * 128 + col, p0, p1);
                    stcs2(abase + (long)(r0 + 8) * S_LEN + kt * 128 + col, p2, p3);
                }
            }
        }
        __syncthreads();

        // ---- O += P @ V (normalized P from smem; R4 mapping) ----
        const __half* vb = vsh + cb * 64 * VSTR;
        #pragma unroll
        for (int kb2 = 0; kb2 < 8; kb2++) {
            uint32_t bv[2][2];
            #pragma unroll
            for (int ni = 0; ni < 2; ni++) {
                uint2 t = *reinterpret_cast<const uint2*>(
                    vb + (wn * 16 + ni * 8 + g) * VSTR + kb2 * 16 + cq * 4);
                bv[ni][0] = t.x; bv[ni][1] = t.y;
            }
            #pragma unroll
            for (int mi = 0; mi < 2; mi++) {
                uint2 lo = *reinterpret_cast<const uint2*>(
                    psh + (wm * 32 + mi * 16 + g) * PSTR + kb2 * 16 + cq * 4);
                uint2 hi = *reinterpret_cast<const uint2*>(
                    psh + (wm * 32 + mi * 16 + g + 8) * PSTR + kb2 * 16 + cq * 4);
                uint32_t a[4] = {lo.x, hi.x, lo.y, hi.y};
                #pragma unroll
                for (int ni = 0; ni < 2; ni++) mma16(o[mi][ni], a, bv[ni]);
            }
        }
    }

    // ---- write O (already normalized) ----
    #pragma unroll
    for (int mi = 0; mi < 2; mi++) {
        int r0 = wm * 32 + mi * 16 + g;
        #pragma unroll
        for (int ni = 0; ni < 2; ni++) {
            int dc = wn * 16 + ni * 8 + 2 * cq;
            *reinterpret_cast<float2*>(obase + (long)r0 * 64 + dc) =
                make_float2(o[mi][ni][0], o[mi][ni][1]);
            *reinterpret_cast<float2*>(obase + (long)(r0 + 8) * 64 + dc) =
                make_float2(o[mi][ni][2], o[mi][ni][3]);
        }
    }
#undef LOAD_K
#undef LOAD_V
}

extern "C" void kernel_launch(void* const* d_in, const int* in_sizes, int n_in,
                              void* d_out, int out_size) {
    const float* q    = (const float*)d_in[0];
    const float* k    = (const float*)d_in[1];
    const float* v    = (const float*)d_in[2];
    const int*   mask = (const int*)d_in[3];

    float* out = (float*)d_out;
    const long OUT_ELEMS  = 2L * 16 * 2048 * 64;
    const long ATTN_ELEMS = 2L * 16 * 2048 * 2048;
    float* attn = ((long)out_size >= OUT_ELEMS + ATTN_ELEMS) ? out + OUT_ELEMS : nullptr;

    prep_k<<<4096, 256>>>(k);
    prep_v<<<dim3(32, 32), 256>>>(v);

    cudaFuncSetAttribute(attn_main, cudaFuncAttributeMaxDynamicSharedMemorySize, SMEM_TOTAL);
    attn_main<<<dim3(16, 32), NTHREADS, SMEM_TOTAL>>>(q, mask, out, attn);
}